// round 16
// baseline (speedup 1.0000x reference)
#include <cuda_runtime.h>
#include <cuda_fp16.h>
#include <cstdint>

// Problem constants (fixed by the dataset instance)
#define BB    2
#define TT    2048
#define DD    1024
#define HH    16
#define HDIM  64
#define NQKV  (3*DD)          // 3072
#define MROWS (BB*TT)         // 4096
#define DW    (DD/2)          // u32 words per D-wide row (512)
#define QW    (NQKV/2)        // u32 words per qkv row (1536)

// q pre-scale: 1/sqrt(hd) * log2(e) -> S is in log2 domain, exp = ex2.approx
#define QSCALE 0.1803368801111204f

// Scratch (allocation-free rule: __device__ globals). All fp16x2-packed (u32).
__device__ uint32_t g_x  [(size_t)MROWS * DW];               // x single fp16
__device__ uint32_t g_wq [(size_t)NQKV  * DW];               // Wqkv single fp16
__device__ uint32_t g_wo [(size_t)DD    * DW];               // Wout  single fp16
__device__ uint32_t g_q  [(size_t)MROWS * QW];               // qkv single fp16 (q pre-scaled)
__device__ uint32_t g_a  [(size_t)MROWS * DW];               // attn single fp16

// ===========================================================================
// Baseline-PTX helpers (no sm_103a-gated instructions).
// ===========================================================================
__device__ __forceinline__ uint32_t smem_u32(const void* p) {
    uint32_t a;
    asm("{ .reg .u64 t; cvta.to.shared.u64 t, %1; cvt.u32.u64 %0, t; }"
        : "=r"(a) : "l"(p));
    return a;
}

__device__ __forceinline__ void ldm_x4(uint32_t r[4], uint32_t addr) {
    asm volatile("ldmatrix.sync.aligned.m8n8.x4.shared.b16 {%0,%1,%2,%3}, [%4];"
                 : "=r"(r[0]), "=r"(r[1]), "=r"(r[2]), "=r"(r[3]) : "r"(addr));
}

__device__ __forceinline__ void ldm_x4_t(uint32_t r[4], uint32_t addr) {
    asm volatile("ldmatrix.sync.aligned.m8n8.x4.trans.shared.b16 {%0,%1,%2,%3}, [%4];"
                 : "=r"(r[0]), "=r"(r[1]), "=r"(r[2]), "=r"(r[3]) : "r"(addr));
}

__device__ __forceinline__ void mma_f16(float c[4], const uint32_t a[4],
                                        uint32_t b0, uint32_t b1) {
    asm volatile(
        "mma.sync.aligned.m16n8k16.row.col.f32.f16.f16.f32 "
        "{%0,%1,%2,%3}, {%4,%5,%6,%7}, {%8,%9}, {%0,%1,%2,%3};"
        : "+f"(c[0]), "+f"(c[1]), "+f"(c[2]), "+f"(c[3])
        : "r"(a[0]), "r"(a[1]), "r"(a[2]), "r"(a[3]), "r"(b0), "r"(b1));
}

// pack two floats into f16x2: first arg -> LOW 16 bits (even-k element)
__device__ __forceinline__ uint32_t packh(float lo, float hi) {
    uint32_t r;
    asm("cvt.rn.f16x2.f32 %0, %1, %2;" : "=r"(r) : "f"(hi), "f"(lo));
    return r;
}

__device__ __forceinline__ float ex2(float x) {
    float y;
    asm("ex2.approx.f32 %0, %1;" : "=f"(y) : "f"(x));
    return y;
}

__device__ __forceinline__ void cp16(uint32_t dst, const uint32_t* src) {
    asm volatile("cp.async.cg.shared.global [%0], [%1], 16;"
                 :: "r"(dst), "l"(src) : "memory");
}
__device__ __forceinline__ void cp_commit() {
    asm volatile("cp.async.commit_group;" ::: "memory");
}
__device__ __forceinline__ void cp_wait0() {
    asm volatile("cp.async.wait_group 0;" ::: "memory");
}

// ===========================================================================
// Pre-pass: fp32 -> single fp16 (packed u32 pairs).
// ===========================================================================
__global__ void conv_f32h(const float4* __restrict__ src, uint2* __restrict__ h,
                          int n4)
{
    int i = blockIdx.x * 256 + threadIdx.x;
    if (i < n4) {
        float4 v = src[i];
        h[i] = make_uint2(packh(v.x, v.y), packh(v.z, v.w));
    }
}

// ===========================================================================
// fp16 GEMM, cp.async 2-stage pipeline, K=64 per stage (round-15 proven).
// C[M,N] = A[M,K] @ B[N,K]^T + bias[N].
// split_out=1: write C single fp16 WITH q-column prescale (qkv GEMM).
// split_out=0: fp32 C32 (output projection).
// ===========================================================================
#define RS 144
#define TILE_B (128 * RS)          // 18432
#define STAGE_B (2 * TILE_B)       // A, B = 36864
#define GK_SMEM (2 * STAGE_B + 128)  // 73856 -> 2 CTA/SM

__global__ void __launch_bounds__(256, 2)
fp16_gemm_async(const uint32_t* __restrict__ A, const uint32_t* __restrict__ B,
                const float* __restrict__ bias,
                float* __restrict__ C32,
                uint32_t* __restrict__ Ch,
                int M, int N, int K, int split_out)
{
    extern __shared__ char smem[];
    const uint32_t sb = (smem_u32(smem) + 127) & ~127u;

    const int tid  = threadIdx.x;
    const int lane = tid & 31;
    const int wid  = tid >> 5;
    const int wm   = wid & 1;
    const int wn   = wid >> 1;
    const int m0   = blockIdx.y * 128;
    const int n0   = blockIdx.x * 128;
    const int Kw   = K >> 1;          // u32 words per row

    float acc[4][4][4];
    #pragma unroll
    for (int i = 0; i < 4; i++)
        #pragma unroll
        for (int j = 0; j < 4; j++)
            #pragma unroll
            for (int q = 0; q < 4; q++) acc[i][j][q] = 0.f;

    const int cr = tid >> 3;          // base row (advances +32 per itx)
    const int cc = tid & 7;           // 16B chunk column

    const uint32_t aLane = (uint32_t)((wm * 64 + (lane & 15)) * RS
                                      + (lane >> 4) * 16);
    const uint32_t bLane = (uint32_t)((wn * 32 + ((lane >> 4) & 1) * 8
                                       + (lane & 7)) * RS
                                      + ((lane >> 3) & 1) * 16);

    const int NIT = K / 64;

    auto issue = [&](int it, int stg) {
        const uint32_t st = sb + (uint32_t)(stg * STAGE_B);
        const int k0w = it * 32;   // u32 words along K (64 fp16)
        #pragma unroll
        for (int itx = 0; itx < 4; itx++) {
            const int r = cr + itx * 32;
            const uint32_t off = (uint32_t)(r * RS + cc * 16);
            cp16(st + off,          A + (size_t)(m0 + r) * Kw + k0w + cc * 4);
            cp16(st + TILE_B + off, B + (size_t)(n0 + r) * Kw + k0w + cc * 4);
        }
        cp_commit();
    };

    issue(0, 0);

    for (int it = 0; it < NIT; ++it) {
        cp_wait0();
        __syncthreads();

        if (it + 1 < NIT) issue(it + 1, (it + 1) & 1);

        const uint32_t cur   = sb + (uint32_t)((it & 1) * STAGE_B);
        const uint32_t aAddr = cur + aLane;
        const uint32_t bAddr = cur + TILE_B + bLane;

        #pragma unroll
        for (int ks = 0; ks < 4; ks++) {
            const uint32_t ko = (uint32_t)(ks * 32);

            uint32_t af[4][4], bf[4][2];
            #pragma unroll
            for (int mi = 0; mi < 4; mi++)
                ldm_x4(af[mi], aAddr + (uint32_t)(mi * 16 * RS) + ko);
            #pragma unroll
            for (int j2 = 0; j2 < 2; j2++) {
                uint32_t t[4];
                ldm_x4(t, bAddr + (uint32_t)(j2 * 16 * RS) + ko);
                bf[2*j2][0] = t[0]; bf[2*j2][1] = t[1];
                bf[2*j2+1][0] = t[2]; bf[2*j2+1][1] = t[3];
            }

            #pragma unroll
            for (int mi = 0; mi < 4; mi++)
                #pragma unroll
                for (int nj = 0; nj < 4; nj++)
                    mma_f16(acc[mi][nj], af[mi], bf[nj][0], bf[nj][1]);
        }
    }

    const int g = lane >> 2;
    const int s = lane & 3;
    if (split_out) {
        const int Nw = N >> 1;
        #pragma unroll
        for (int mi = 0; mi < 4; mi++) {
            const int mrow = m0 + wm * 64 + mi * 16 + g;
            #pragma unroll
            for (int nj = 0; nj < 4; nj++) {
                const int ncol = n0 + wn * 32 + nj * 8 + s * 2;
                // q columns (col%192 < 64) pre-scaled by 0.125*log2(e)
                const float qs = ((ncol % 192) < 64) ? QSCALE : 1.0f;
                float2 bv = *(const float2*)(bias + ncol);
                Ch[(size_t)mrow * Nw + (ncol >> 1)] =
                    packh((acc[mi][nj][0] + bv.x) * qs,
                          (acc[mi][nj][1] + bv.y) * qs);
                Ch[(size_t)(mrow + 8) * Nw + (ncol >> 1)] =
                    packh((acc[mi][nj][2] + bv.x) * qs,
                          (acc[mi][nj][3] + bv.y) * qs);
            }
        }
    } else {
        #pragma unroll
        for (int mi = 0; mi < 4; mi++) {
            const int mrow = m0 + wm * 64 + mi * 16 + g;
            #pragma unroll
            for (int nj = 0; nj < 4; nj++) {
                const int ncol = n0 + wn * 32 + nj * 8 + s * 2;
                float2 bv = *(const float2*)(bias + ncol);
                float2 o0, o1;
                o0.x = acc[mi][nj][0] + bv.x;  o0.y = acc[mi][nj][1] + bv.y;
                o1.x = acc[mi][nj][2] + bv.x;  o1.y = acc[mi][nj][3] + bv.y;
                *(float2*)(C32 + (size_t)mrow * N + ncol)       = o0;
                *(float2*)(C32 + (size_t)(mrow + 8) * N + ncol) = o1;
            }
        }
    }
}

// ===========================================================================
// Tensor-core flash attention (causal), single fp16, 128-KEY BLOCKS:
// one online-softmax pass per 128 keys (halved shuffles/rescale/syncs).
// Q pre-scaled (log2 domain) -> exp via ex2.approx.
// 64-row Q tile, 128 threads / 4 warps, cp.async double-buffered K/V.
// Only the LAST 128-key block intersects the diagonal (proven for all iq).
// ===========================================================================
#define AT_RS    144
#define AT_T64   (64 * AT_RS)                // 9216
#define AT_T128  (128 * AT_RS)               // 18432
#define AT_KV0   AT_T64                      // stage s at AT_KV0 + s*2*AT_T128
#define AT_SMEM  (AT_T64 + 2 * 2 * AT_T128 + 128)   // 83072

__global__ void __launch_bounds__(128)
flash_attn_mma(const uint32_t* __restrict__ qkv, uint32_t* __restrict__ ao)
{
    extern __shared__ char smem[];
    const uint32_t sb = (smem_u32(smem) + 127) & ~127u;

    const int iq   = (int)gridDim.x - 1 - (int)blockIdx.x;   // heavy first
    const int h    = blockIdx.y;
    const int b    = blockIdx.z;
    const int tid  = threadIdx.x;
    const int lane = tid & 31;
    const int w    = tid >> 5;

    const uint32_t* base = qkv + (size_t)b * TT * QW + h * 96;  // h*192 fp16

    // Q: 64 rows x 8 chunks(16B) = 512 chunks
    {
        #pragma unroll
        for (int itx = 0; itx < 4; itx++) {
            const int f = tid + itx * 128;
            const int r = f >> 3, c = f & 7;
            cp16(sb + (uint32_t)(r * AT_RS + c * 16),
                 base + (size_t)(iq * 64 + r) * QW + c * 4);
        }
    }
    // K/V: 128 rows x 8 chunks each per stage
    auto issueKV = [&](int jj, int stg) {
        const uint32_t st = sb + AT_KV0 + (uint32_t)(stg * 2 * AT_T128);
        #pragma unroll
        for (int itx = 0; itx < 8; itx++) {
            const int f = tid + itx * 128;
            const int r = f >> 3, c = f & 7;
            const size_t go = (size_t)(jj * 128 + r) * QW + 32 + c * 4;  // K words
            const uint32_t off = (uint32_t)(r * AT_RS + c * 16);
            cp16(st + off,           base + go);        // K
            cp16(st + AT_T128 + off, base + go + 32);   // V
        }
    };

    const int nb = (iq + 2) >> 1;   // ceil((iq+1)*64 / 128)

    issueKV(0, 0);
    cp_commit();

    const int g = lane >> 2;
    const int s = lane & 3;

    const uint32_t aQ = sb +
        (uint32_t)((w * 16 + (lane & 15)) * AT_RS + (lane >> 4) * 16);
    const uint32_t kLane =
        (uint32_t)((((lane >> 4) & 1) * 8 + (lane & 7)) * AT_RS
                   + ((lane >> 3) & 1) * 16);
    const uint32_t vLane =
        (uint32_t)((((lane >> 3) & 1) * 8 + (lane & 7)) * AT_RS
                   + ((lane >> 4) & 1) * 16);

    float m0v = -1e30f, m1v = -1e30f, l0v = 0.f, l1v = 0.f;
    float o[8][4];
    #pragma unroll
    for (int nt = 0; nt < 8; nt++)
        #pragma unroll
        for (int q = 0; q < 4; q++) o[nt][q] = 0.f;

    const int qrow0 = iq * 64 + w * 16 + g;

    for (int jj = 0; jj < nb; jj++) {
        const int cur = jj & 1;
        cp_wait0();
        __syncthreads();
        if (jj + 1 < nb) {
            issueKV(jj + 1, cur ^ 1);
            cp_commit();
        }

        const uint32_t st = sb + AT_KV0 + (uint32_t)(cur * 2 * AT_T128);
        const uint32_t bK = st + kLane;
        const uint32_t bV = st + AT_T128 + vLane;

        // ---- S = Q @ K^T over 128 keys (fp32 accum, log2 domain) ----
        float sacc[16][4];
        #pragma unroll
        for (int nt = 0; nt < 16; nt++)
            #pragma unroll
            for (int q = 0; q < 4; q++) sacc[nt][q] = 0.f;

        #pragma unroll
        for (int ks = 0; ks < 4; ks++) {
            const uint32_t ko = (uint32_t)(ks * 32);
            uint32_t qf[4];
            ldm_x4(qf, aQ + ko);
            #pragma unroll
            for (int nb2 = 0; nb2 < 8; nb2++) {
                uint32_t t[4];
                ldm_x4(t, bK + (uint32_t)(nb2 * 16 * AT_RS) + ko);
                mma_f16(sacc[2*nb2],   qf, t[0], t[1]);
                mma_f16(sacc[2*nb2+1], qf, t[2], t[3]);
            }
        }

        // ---- causal mask (only the last block intersects the diagonal) ----
        if (jj == nb - 1) {
            #pragma unroll
            for (int nt = 0; nt < 16; nt++) {
                const int col = jj * 128 + nt * 8 + s * 2;
                if (col     > qrow0)     sacc[nt][0] = -1e30f;
                if (col + 1 > qrow0)     sacc[nt][1] = -1e30f;
                if (col     > qrow0 + 8) sacc[nt][2] = -1e30f;
                if (col + 1 > qrow0 + 8) sacc[nt][3] = -1e30f;
            }
        }

        // ---- online softmax (one pass per 128 keys) ----
        float mx0 = -1e30f, mx1 = -1e30f;
        #pragma unroll
        for (int nt = 0; nt < 16; nt++) {
            mx0 = fmaxf(mx0, fmaxf(sacc[nt][0], sacc[nt][1]));
            mx1 = fmaxf(mx1, fmaxf(sacc[nt][2], sacc[nt][3]));
        }
        mx0 = fmaxf(mx0, __shfl_xor_sync(0xffffffffu, mx0, 1));
        mx0 = fmaxf(mx0, __shfl_xor_sync(0xffffffffu, mx0, 2));
        mx1 = fmaxf(mx1, __shfl_xor_sync(0xffffffffu, mx1, 1));
        mx1 = fmaxf(mx1, __shfl_xor_sync(0xffffffffu, mx1, 2));

        const float mn0 = fmaxf(m0v, mx0);
        const float mn1 = fmaxf(m1v, mx1);
        const float cr0 = ex2(m0v - mn0);
        const float cr1 = ex2(m1v - mn1);

        float rs0 = 0.f, rs1 = 0.f;
        #pragma unroll
        for (int nt = 0; nt < 16; nt++) {
            float p0 = ex2(sacc[nt][0] - mn0);
            float p1 = ex2(sacc[nt][1] - mn0);
            float p2 = ex2(sacc[nt][2] - mn1);
            float p3 = ex2(sacc[nt][3] - mn1);
            sacc[nt][0] = p0; sacc[nt][1] = p1;
            sacc[nt][2] = p2; sacc[nt][3] = p3;
            rs0 += p0 + p1;
            rs1 += p2 + p3;
        }
        rs0 += __shfl_xor_sync(0xffffffffu, rs0, 1);
        rs0 += __shfl_xor_sync(0xffffffffu, rs0, 2);
        rs1 += __shfl_xor_sync(0xffffffffu, rs1, 1);
        rs1 += __shfl_xor_sync(0xffffffffu, rs1, 2);

        l0v = l0v * cr0 + rs0;
        l1v = l1v * cr1 + rs1;
        m0v = mn0;
        m1v = mn1;
        #pragma unroll
        for (int nt = 0; nt < 8; nt++) {
            o[nt][0] *= cr0; o[nt][1] *= cr0;
            o[nt][2] *= cr1; o[nt][3] *= cr1;
        }

        // ---- O += P @ V (P single fp16 from registers, V via ldm.trans) ----
        #pragma unroll
        for (int ks2 = 0; ks2 < 8; ks2++) {
            uint32_t ph[4];
            ph[0] = packh(sacc[2*ks2][0],   sacc[2*ks2][1]);
            ph[1] = packh(sacc[2*ks2][2],   sacc[2*ks2][3]);
            ph[2] = packh(sacc[2*ks2+1][0], sacc[2*ks2+1][1]);
            ph[3] = packh(sacc[2*ks2+1][2], sacc[2*ks2+1][3]);

            const uint32_t krow = (uint32_t)(ks2 * 16 * AT_RS);
            #pragma unroll
            for (int nb2 = 0; nb2 < 4; nb2++) {
                uint32_t t[4];
                ldm_x4_t(t, bV + krow + (uint32_t)(nb2 * 32));
                mma_f16(o[2*nb2],   ph, t[0], t[1]);
                mma_f16(o[2*nb2+1], ph, t[2], t[3]);
            }
        }
    }

    // ---- epilogue: normalize, write attn single fp16 [B*T, D/2 u32] ----
    const float inv0 = 1.f / l0v;
    const float inv1 = 1.f / l1v;
    const size_t r0 = (size_t)b * TT + iq * 64 + w * 16 + g;
    #pragma unroll
    for (int nt = 0; nt < 8; nt++) {
        const int colw = h * 32 + nt * 4 + s;   // u32 column
        ao[r0 * DW + colw]       = packh(o[nt][0] * inv0, o[nt][1] * inv0);
        ao[(r0 + 8) * DW + colw] = packh(o[nt][2] * inv1, o[nt][3] * inv1);
    }
}

// ===========================================================================
// Launch: convs -> qkv GEMM (fp16-out, q pre-scaled) -> flash -> out GEMM.
// ===========================================================================
extern "C" void kernel_launch(void* const* d_in, const int* in_sizes, int n_in,
                              void* d_out, int out_size)
{
    const float* x    = (const float*)d_in[0];
    const float* Wqkv = (const float*)d_in[1];
    const float* bqkv = (const float*)d_in[2];
    const float* Wout = (const float*)d_in[3];
    const float* bout = (const float*)d_in[4];
    float*       out  = (float*)d_out;

    uint32_t *xp, *wq, *wo, *qp, *ap;
    cudaGetSymbolAddress((void**)&xp, g_x);
    cudaGetSymbolAddress((void**)&wq, g_wq);
    cudaGetSymbolAddress((void**)&wo, g_wo);
    cudaGetSymbolAddress((void**)&qp, g_q);
    cudaGetSymbolAddress((void**)&ap, g_a);

    cudaFuncSetAttribute(fp16_gemm_async,
                         cudaFuncAttributeMaxDynamicSharedMemorySize, GK_SMEM);
    cudaFuncSetAttribute(flash_attn_mma,
                         cudaFuncAttributeMaxDynamicSharedMemorySize, AT_SMEM);

    // 0) pre-passes: fp32 -> single fp16
    {
        int n4;
        n4 = MROWS * DD / 4;
        conv_f32h<<<(n4 + 255) / 256, 256>>>((const float4*)x, (uint2*)xp, n4);
        n4 = NQKV * DD / 4;
        conv_f32h<<<(n4 + 255) / 256, 256>>>((const float4*)Wqkv, (uint2*)wq, n4);
        n4 = DD * DD / 4;
        conv_f32h<<<(n4 + 255) / 256, 256>>>((const float4*)Wout, (uint2*)wo, n4);
    }
    // 1) qkv = x @ Wqkv^T + bqkv -> single fp16 (q cols pre-scaled)
    {
        dim3 grid(NQKV / 128, MROWS / 128);   // (24, 32)
        fp16_gemm_async<<<grid, 256, GK_SMEM>>>(xp, wq, bqkv,
                                                nullptr, qp,
                                                MROWS, NQKV, DD, 1);
    }
    // 2) attention -> single fp16 (64-row Q tiles, 128-key blocks)
    {
        dim3 grid(TT / 64, HH, BB);           // (32, 16, 2)
        flash_attn_mma<<<grid, 128, AT_SMEM>>>(qp, ap);
    }
    // 3) out = attn @ Wout^T + bout (fp32)
    {
        dim3 grid(DD / 128, MROWS / 128);     // (8, 32)
        fp16_gemm_async<<<grid, 256, GK_SMEM>>>(ap, wo, bout,
                                                out, nullptr,
                                                MROWS, DD, DD, 0);
    }
}